// round 12
// baseline (speedup 1.0000x reference)
#include <cuda_runtime.h>

// Round 12: pair-interleaved smem (u64 column pairs (c, c+8)) so tf32 mma
// fragments load via LDS.64: 48 -> 24 LDS per thread per k8, STS 32 -> 16.
// Split still at staging time (R11). Attention = R6 measured-best, untouched.

#define EMBED 1024
#define NHEAD 16
#define HDIM  64
#define BATCH 2
#define SEQ   2048
#define MTOT  (BATCH*SEQ)

#define PBM 128
#define PBN 128
#define PBK 16
#define PR   68     // u64 row stride (68 mod 16 == 4 -> conflict-free phases)

#define PADP 68
#define ATTN_FLOATS (3*64*PADP + 128)
#define ATTN_SMEM   (ATTN_FLOATS*4)

typedef unsigned long long u64;
typedef unsigned int u32;

// ---- f32x2 helpers (attention) ----
__device__ __forceinline__ u64 pk2(float a) {
    u64 r; asm("mov.b64 %0, {%1, %1};" : "=l"(r) : "f"(a)); return r;
}
__device__ __forceinline__ void fma2(u64& d, u64 a, u64 b) {
    asm("fma.rn.f32x2 %0, %1, %2, %0;" : "+l"(d) : "l"(a), "l"(b));
}
__device__ __forceinline__ void mul2(u64& d, u64 a) {
    asm("mul.rn.f32x2 %0, %0, %1;" : "+l"(d) : "l"(a));
}
__device__ __forceinline__ float2 up2(u64 v) {
    float2 r; asm("mov.b64 {%0, %1}, %2;" : "=f"(r.x), "=f"(r.y) : "l"(v)); return r;
}

// ---- tf32 helpers ----
__device__ __forceinline__ void split_tf32(float a, u32& hi, u32& lo) {
    asm("cvt.rna.tf32.f32 %0, %1;" : "=r"(hi) : "f"(a));
    float r = a - __uint_as_float(hi);
    asm("cvt.rna.tf32.f32 %0, %1;" : "=r"(lo) : "f"(r));
}
__device__ __forceinline__ void mma8(float* c, const u32* a, const u32* b) {
    asm("mma.sync.aligned.m16n8k8.row.col.f32.tf32.tf32.f32 "
        "{%0,%1,%2,%3}, {%4,%5,%6,%7}, {%8,%9}, {%0,%1,%2,%3};"
        : "+f"(c[0]), "+f"(c[1]), "+f"(c[2]), "+f"(c[3])
        : "r"(a[0]), "r"(a[1]), "r"(a[2]), "r"(a[3]), "r"(b[0]), "r"(b[1]));
}

__device__ float g_q[BATCH*NHEAD*SEQ*HDIM];
__device__ float g_k[BATCH*NHEAD*SEQ*HDIM];
__device__ float g_v[BATCH*NHEAD*SEQ*HDIM];
__device__ float g_h[MTOT*EMBED];

// ---------------------------------------------------------------------------
// 128x128 tf32-mma GEMM body. Pair-interleaved smem: column-pair index
// cp(c) = (c>>4)*8 + (c&7) holds (c, c+8) as a uint2.
// Staging: thread owns col-pair (tid&63) and 4 k's ((tid>>6)*4).
// 8 warps as 2(m) x 4(n); warp tile 64x32; 3 mma per tile per k8.
// ---------------------------------------------------------------------------
#define PROJ_MMA_BODY(APTR, WPTR)                                              \
    __shared__ uint2 A2h[PBK][PR];                                             \
    __shared__ uint2 A2l[PBK][PR];                                             \
    __shared__ uint2 B2h[PBK][PR];                                             \
    __shared__ uint2 B2l[PBK][PR];                                             \
    const int tid  = threadIdx.x;                                              \
    const int lane = tid & 31;                                                 \
    const int wid  = tid >> 5;                                                 \
    const int m0 = blockIdx.y * PBM;                                           \
    const int n0 = blockIdx.x * PBN;                                           \
    const int wm = (wid >> 2) << 6;                                            \
    const int wn = (wid & 3) << 5;                                             \
    const int g4 = lane >> 2;                                                  \
    const int t4 = lane & 3;                                                   \
    const int cp  = tid & 63;                                                  \
    const int cc  = ((cp >> 3) << 4) + (cp & 7);   /* col of pair */           \
    const int k0s = (tid >> 6) << 2;               /* 0,4,8,12 */              \
    const float* Ap0 = (APTR) + (size_t)(m0 + cc    ) * EMBED + k0s;           \
    const float* Ap1 = (APTR) + (size_t)(m0 + cc + 8) * EMBED + k0s;           \
    const float* Wp0 = (WPTR) + (size_t)(n0 + cc    ) * EMBED + k0s;           \
    const float* Wp1 = (WPTR) + (size_t)(n0 + cc + 8) * EMBED + k0s;           \
    float c[4][4][4];                                                          \
    _Pragma("unroll")                                                          \
    for (int mi = 0; mi < 4; mi++)                                             \
        _Pragma("unroll")                                                      \
        for (int ni = 0; ni < 4; ni++)                                         \
            _Pragma("unroll")                                                  \
            for (int u = 0; u < 4; u++) c[mi][ni][u] = 0.f;                    \
    float4 ga0 = *(const float4*)(Ap0);                                        \
    float4 ga1 = *(const float4*)(Ap1);                                        \
    float4 gw0 = *(const float4*)(Wp0);                                        \
    float4 gw1 = *(const float4*)(Wp1);                                        \
    for (int kb = 0; kb < EMBED; kb += PBK) {                                  \
        __syncthreads();                                                       \
        {                                                                      \
            const float av0[4] = {ga0.x, ga0.y, ga0.z, ga0.w};                 \
            const float av1[4] = {ga1.x, ga1.y, ga1.z, ga1.w};                 \
            const float wv0[4] = {gw0.x, gw0.y, gw0.z, gw0.w};                 \
            const float wv1[4] = {gw1.x, gw1.y, gw1.z, gw1.w};                 \
            _Pragma("unroll")                                                  \
            for (int j = 0; j < 4; j++) {                                      \
                u32 h0, l0, h1, l1;                                            \
                split_tf32(av0[j], h0, l0);                                    \
                split_tf32(av1[j], h1, l1);                                    \
                A2h[k0s+j][cp] = make_uint2(h0, h1);                           \
                A2l[k0s+j][cp] = make_uint2(l0, l1);                           \
                split_tf32(wv0[j], h0, l0);                                    \
                split_tf32(wv1[j], h1, l1);                                    \
                B2h[k0s+j][cp] = make_uint2(h0, h1);                           \
                B2l[k0s+j][cp] = make_uint2(l0, l1);                           \
            }                                                                  \
        }                                                                      \
        __syncthreads();                                                       \
        if (kb + PBK < EMBED) {                                                \
            ga0 = *(const float4*)(Ap0 + kb + PBK);                            \
            ga1 = *(const float4*)(Ap1 + kb + PBK);                            \
            gw0 = *(const float4*)(Wp0 + kb + PBK);                            \
            gw1 = *(const float4*)(Wp1 + kb + PBK);                            \
        }                                                                      \
        _Pragma("unroll")                                                      \
        for (int k8 = 0; k8 < PBK; k8 += 8) {                                  \
            const int pb0 = ((wn >> 4)) * 8 + g4;                              \
            uint2 bh0a = B2h[k8+t4  ][pb0], bh0b = B2h[k8+t4+4][pb0];          \
            uint2 bh1a = B2h[k8+t4  ][pb0+8], bh1b = B2h[k8+t4+4][pb0+8];      \
            uint2 bl0a = B2l[k8+t4  ][pb0], bl0b = B2l[k8+t4+4][pb0];          \
            uint2 bl1a = B2l[k8+t4  ][pb0+8], bl1b = B2l[k8+t4+4][pb0+8];      \
            u32 bhi[4][2] = {{bh0a.x, bh0b.x}, {bh0a.y, bh0b.y},               \
                             {bh1a.x, bh1b.x}, {bh1a.y, bh1b.y}};              \
            u32 blo[4][2] = {{bl0a.x, bl0b.x}, {bl0a.y, bl0b.y},               \
                             {bl1a.x, bl1b.x}, {bl1a.y, bl1b.y}};              \
            _Pragma("unroll")                                                  \
            for (int mi = 0; mi < 4; mi++) {                                   \
                const int pa = ((wm >> 4) + mi) * 8 + g4;                      \
                uint2 ahA = A2h[k8+t4  ][pa], ahB = A2h[k8+t4+4][pa];          \
                uint2 alA = A2l[k8+t4  ][pa], alB = A2l[k8+t4+4][pa];          \
                u32 ahi[4] = {ahA.x, ahA.y, ahB.x, ahB.y};                     \
                u32 alo[4] = {alA.x, alA.y, alB.x, alB.y};                     \
                _Pragma("unroll")                                              \
                for (int ni = 0; ni < 4; ni++) {                               \
                    mma8(c[mi][ni], ahi, bhi[ni]);                             \
                    mma8(c[mi][ni], ahi, blo[ni]);                             \
                    mma8(c[mi][ni], alo, bhi[ni]);                             \
                }                                                              \
            }                                                                  \
        }                                                                      \
    }

// ---------------------------------------------------------------------------
__global__ __launch_bounds__(256, 2) void qkv_proj_kernel(
    const float* __restrict__ X,
    const float* __restrict__ Wq, const float* __restrict__ bq,
    const float* __restrict__ Wk, const float* __restrict__ bk,
    const float* __restrict__ Wv, const float* __restrict__ bv)
{
    const int z = blockIdx.z;
    const float *W, *bias; float* Out;
    if (z == 0)      { W = Wq; bias = bq; Out = g_q; }
    else if (z == 1) { W = Wk; bias = bk; Out = g_k; }
    else             { W = Wv; bias = bv; Out = g_v; }

    PROJ_MMA_BODY(X, W)

#pragma unroll
    for (int mi = 0; mi < 4; mi++) {
#pragma unroll
        for (int ni = 0; ni < 4; ni++) {
            const int col = n0 + wn + ni*8 + 2*t4;
            const int h   = col >> 6;
            const int d   = col & 63;
            float2 bb = *(const float2*)&bias[col];
#pragma unroll
            for (int half = 0; half < 2; half++) {
                int row = m0 + wm + mi*16 + g4 + half*8;
                int b   = row >> 11;
                int n   = row & (SEQ - 1);
                float2 o = make_float2(c[mi][ni][2*half+0] + bb.x,
                                       c[mi][ni][2*half+1] + bb.y);
                *(float2*)&Out[((size_t)(b*NHEAD + h)*SEQ + n)*HDIM + d] = o;
            }
        }
    }
}

// ---------------------------------------------------------------------------
__global__ __launch_bounds__(256, 2) void out_proj_kernel(
    const float* __restrict__ Wo, const float* __restrict__ bo,
    float* __restrict__ Outp)
{
    PROJ_MMA_BODY(g_h, Wo)

#pragma unroll
    for (int mi = 0; mi < 4; mi++) {
#pragma unroll
        for (int ni = 0; ni < 4; ni++) {
            const int col = n0 + wn + ni*8 + 2*t4;
            float2 bb = *(const float2*)&bo[col];
#pragma unroll
            for (int half = 0; half < 2; half++) {
                int row = m0 + wm + mi*16 + g4 + half*8;
                float2 o = make_float2(c[mi][ni][2*half+0] + bb.x,
                                       c[mi][ni][2*half+1] + bb.y);
                *(float2*)&Outp[(size_t)row * EMBED + col] = o;
            }
        }
    }
}

// ---------------------------------------------------------------------------
// Flash attention (R6 measured-best): f32x2 inner loops, shared K/V buffer.
// ---------------------------------------------------------------------------
__global__ __launch_bounds__(256, 2) void attn_kernel()
{
    extern __shared__ float sm[];
    float* Qs  = sm;
    float* KVs = sm + 64*PADP;
    float* Ps  = sm + 2*64*PADP;
    float* corr_s = sm + 3*64*PADP;
    float* l_s    = corr_s + 64;

    const int tid = threadIdx.x;
    const int bh  = blockIdx.y;
    const int q0  = blockIdx.x << 6;
    const float* Qg = g_q + (size_t)bh * SEQ * HDIM;
    const float* Kg = g_k + (size_t)bh * SEQ * HDIM;
    const float* Vg = g_v + (size_t)bh * SEQ * HDIM;

    const int lr = tid >> 2;
    const int ty = tid >> 4;
    const int tx = tid & 15;
    const int g   = tid >> 6;
    const int t64 = tid & 63;
    const int tr  = t64 >> 3;
    const int tc  = t64 & 7;

#pragma unroll
    for (int it = 0; it < 4; it++) {
        int d = it * 16 + ((tid & 3) << 2);
        float4 v = *(const float4*)&Qg[(size_t)(q0 + lr) * HDIM + d];
        Qs[(d+0)*PADP + lr] = v.x;  Qs[(d+1)*PADP + lr] = v.y;
        Qs[(d+2)*PADP + lr] = v.z;  Qs[(d+3)*PADP + lr] = v.w;
    }

    float m_run[4], l_run[4];
    u64 o2[8][4];
#pragma unroll
    for (int i = 0; i < 4; i++) { m_run[i] = -1e30f; l_run[i] = 0.f; }
#pragma unroll
    for (int i = 0; i < 8; i++)
#pragma unroll
        for (int j = 0; j < 4; j++) o2[i][j] = 0ull;

    for (int k0 = 0; k0 < SEQ; k0 += 64) {
        __syncthreads();
#pragma unroll
        for (int it = 0; it < 4; it++) {
            int d = it * 16 + ((tid & 3) << 2);
            float4 kv = *(const float4*)&Kg[(size_t)(k0 + lr) * HDIM + d];
            KVs[(d+0)*PADP + lr] = kv.x;  KVs[(d+1)*PADP + lr] = kv.y;
            KVs[(d+2)*PADP + lr] = kv.z;  KVs[(d+3)*PADP + lr] = kv.w;
        }
        __syncthreads();

        u64 s2[4][2] = {{0ull,0ull},{0ull,0ull},{0ull,0ull},{0ull,0ull}};
#pragma unroll 8
        for (int d = 0; d < 64; d++) {
            float4 av = *(const float4*)&Qs[d*PADP + (ty<<2)];
            const u64* bp = (const u64*)&KVs[d*PADP + (tx<<2)];
            u64 b0 = bp[0], b1 = bp[1];
            float ar[4] = {av.x, av.y, av.z, av.w};
#pragma unroll
            for (int i = 0; i < 4; i++) {
                u64 av2 = pk2(ar[i]);
                fma2(s2[i][0], av2, b0);
                fma2(s2[i][1], av2, b1);
            }
        }

#pragma unroll
        for (int i = 0; i < 4; i++) {
            float2 q0p = up2(s2[i][0]), q1p = up2(s2[i][1]);
            float s[4] = {q0p.x*8.0f, q0p.y*8.0f, q1p.x*8.0f, q1p.y*8.0f};
            float mx = fmaxf(fmaxf(s[0], s[1]), fmaxf(s[2], s[3]));
            mx = fmaxf(mx, __shfl_xor_sync(0xffffffffu, mx, 8, 16));
            mx = fmaxf(mx, __shfl_xor_sync(0xffffffffu, mx, 4, 16));
            mx = fmaxf(mx, __shfl_xor_sync(0xffffffffu, mx, 2, 16));
            mx = fmaxf(mx, __shfl_xor_sync(0xffffffffu, mx, 1, 16));
            float mnew = fmaxf(m_run[i], mx);
            float corr = __expf(m_run[i] - mnew);
            float rs = 0.f;
#pragma unroll
            for (int j = 0; j < 4; j++) {
                float p = __expf(s[j] - mnew);
                s[j] = p; rs += p;
            }
            rs += __shfl_xor_sync(0xffffffffu, rs, 8, 16);
            rs += __shfl_xor_sync(0xffffffffu, rs, 4, 16);
            rs += __shfl_xor_sync(0xffffffffu, rs, 2, 16);
            rs += __shfl_xor_sync(0xffffffffu, rs, 1, 16);
            l_run[i] = l_run[i] * corr + rs;
            m_run[i] = mnew;
            if (tx == 0) corr_s[(ty<<2)+i] = corr;
            *(float4*)&Ps[((ty<<2)+i)*PADP + (tx<<2)] =
                make_float4(s[0], s[1], s[2], s[3]);
        }
        __syncthreads();

#pragma unroll
        for (int it = 0; it < 4; it++) {
            int d = it * 16 + ((tid & 3) << 2);
            float4 vv = *(const float4*)&Vg[(size_t)(k0 + lr) * HDIM + d];
            *(float4*)&KVs[lr * PADP + d] = vv;
        }
        __syncthreads();

#pragma unroll
        for (int rr = 0; rr < 8; rr++) {
            u64 c2 = pk2(corr_s[tr*8 + rr]);
            mul2(o2[rr][0], c2); mul2(o2[rr][1], c2);
            mul2(o2[rr][2], c2); mul2(o2[rr][3], c2);
        }

        const int kbase = g << 4;
#pragma unroll
        for (int c4 = 0; c4 < 16; c4 += 4) {
            const int kk = kbase + c4;
            u64 v2[4][4];
#pragma unroll
            for (int u = 0; u < 4; u++) {
                const u64* vp0 = (const u64*)&KVs[(kk+u)*PADP + (tc<<2)];
                const u64* vp1 = (const u64*)&KVs[(kk+u)*PADP + 32 + (tc<<2)];
                v2[u][0] = vp0[0]; v2[u][1] = vp0[1];
                v2[u][2] = vp1[0]; v2[u][3] = vp1[1];
            }
#pragma unroll
            for (int rr = 0; rr < 8; rr++) {
                float4 p = *(const float4*)&Ps[(tr*8+rr)*PADP + kk];
                float pa[4] = {p.x, p.y, p.z, p.w};
#pragma unroll
                for (int u = 0; u < 4; u++) {
                    u64 p2 = pk2(pa[u]);
                    fma2(o2[rr][0], p2, v2[u][0]);
                    fma2(o2[rr][1], p2, v2[u][1]);
                    fma2(o2[rr][2], p2, v2[u][2]);
                    fma2(o2[rr][3], p2, v2[u][3]);
                }
            }
        }
    }

    float o[8][8];
#pragma unroll
    for (int rr = 0; rr < 8; rr++) {
        float2 p0 = up2(o2[rr][0]), p1 = up2(o2[rr][1]);
        float2 p2 = up2(o2[rr][2]), p3 = up2(o2[rr][3]);
        o[rr][0]=p0.x; o[rr][1]=p0.y; o[rr][2]=p1.x; o[rr][3]=p1.y;
        o[rr][4]=p2.x; o[rr][5]=p2.y; o[rr][6]=p3.x; o[rr][7]=p3.y;
    }

    if (tx == 0) {
#pragma unroll
        for (int i = 0; i < 4; i++) l_s[(ty<<2)+i] = l_run[i];
    }
    __syncthreads();

    if (g > 0) {
        float* mb = sm + (g-1)*(64*PADP) + t64*PADP;
#pragma unroll
        for (int rr = 0; rr < 8; rr++) {
            *(float4*)&mb[rr*8 + 0] = make_float4(o[rr][0], o[rr][1], o[rr][2], o[rr][3]);
            *(float4*)&mb[rr*8 + 4] = make_float4(o[rr][4], o[rr][5], o[rr][6], o[rr][7]);
        }
    }
    __syncthreads();

    if (g == 0) {
        const int b = bh >> 4;
        const int h = bh & 15;
#pragma unroll
        for (int gg = 0; gg < 3; gg++) {
            const float* mb = sm + gg*(64*PADP) + t64*PADP;
#pragma unroll
            for (int rr = 0; rr < 8; rr++) {
                float4 p0 = *(const float4*)&mb[rr*8 + 0];
                float4 p1 = *(const float4*)&mb[rr*8 + 4];
                o[rr][0] += p0.x; o[rr][1] += p0.y; o[rr][2] += p0.z; o[rr][3] += p0.w;
                o[rr][4] += p1.x; o[rr][5] += p1.y; o[rr][6] += p1.z; o[rr][7] += p1.w;
            }
        }
#pragma unroll
        for (int rr = 0; rr < 8; rr++) {
            int row = tr*8 + rr;
            float inv = 1.0f / l_s[row];
            int q = q0 + row;
            float* dst = &g_h[((size_t)(b*SEQ + q))*EMBED + h*HDIM];
            *(float4*)&dst[(tc<<2)] =
                make_float4(o[rr][0]*inv, o[rr][1]*inv, o[rr][2]*inv, o[rr][3]*inv);
            *(float4*)&dst[32 + (tc<<2)] =
                make_float4(o[rr][4]*inv, o[rr][5]*inv, o[rr][6]*inv, o[rr][7]*inv);
        }
    }
}

// ---------------------------------------------------------------------------
extern "C" void kernel_launch(void* const* d_in, const int* in_sizes, int n_in,
                              void* d_out, int out_size)
{
    const float* x  = (const float*)d_in[0];
    const float* Wq = (const float*)d_in[1];
    const float* bq = (const float*)d_in[2];
    const float* Wk = (const float*)d_in[3];
    const float* bk = (const float*)d_in[4];
    const float* Wv = (const float*)d_in[5];
    const float* bv = (const float*)d_in[6];
    const float* Wo = (const float*)d_in[7];
    const float* bo = (const float*)d_in[8];
    float* out = (float*)d_out;

    cudaFuncSetAttribute(attn_kernel,
                         cudaFuncAttributeMaxDynamicSharedMemorySize, ATTN_SMEM);

    dim3 gproj(EMBED / PBN, MTOT / PBM, 3);
    qkv_proj_kernel<<<gproj, 256>>>(x, Wq, bq, Wk, bk, Wv, bv);

    dim3 gattn(SEQ / 64, BATCH * NHEAD);
    attn_kernel<<<gattn, 256, ATTN_SMEM>>>();

    dim3 gout(EMBED / PBN, MTOT / PBM);
    out_proj_kernel<<<gout, 256>>>(Wo, bo, out);
}

// round 14
// speedup vs baseline: 1.0322x; 1.0322x over previous
#include <cuda_runtime.h>

// Round 14 = Round 13 resubmit (infra failed; kernel never ran).
// R11 base + k-pair-interleaved smem (uint2 holds k and k+4) so tf32
// fragments load via LDS.64 (48 -> 24 LDS/thread/k8) while keeping R11's
// EXACT coalesced global load pattern (R12 broke coalescing; this does not).
// Attention = R6 measured-best, untouched.

#define EMBED 1024
#define NHEAD 16
#define HDIM  64
#define BATCH 2
#define SEQ   2048
#define MTOT  (BATCH*SEQ)

#define PBM 128
#define PBN 128
#define PBK 16
#define PRW  132    // uint2 cols per pair-row; 2*132 mod 32 = 8 -> conflict-free loads

#define PADP 68
#define ATTN_FLOATS (3*64*PADP + 128)
#define ATTN_SMEM   (ATTN_FLOATS*4)

typedef unsigned long long u64;
typedef unsigned int u32;

// ---- f32x2 helpers (attention) ----
__device__ __forceinline__ u64 pk2(float a) {
    u64 r; asm("mov.b64 %0, {%1, %1};" : "=l"(r) : "f"(a)); return r;
}
__device__ __forceinline__ void fma2(u64& d, u64 a, u64 b) {
    asm("fma.rn.f32x2 %0, %1, %2, %0;" : "+l"(d) : "l"(a), "l"(b));
}
__device__ __forceinline__ void mul2(u64& d, u64 a) {
    asm("mul.rn.f32x2 %0, %0, %1;" : "+l"(d) : "l"(a));
}
__device__ __forceinline__ float2 up2(u64 v) {
    float2 r; asm("mov.b64 {%0, %1}, %2;" : "=f"(r.x), "=f"(r.y) : "l"(v)); return r;
}

// ---- tf32 helpers ----
__device__ __forceinline__ void split_tf32(float a, u32& hi, u32& lo) {
    asm("cvt.rna.tf32.f32 %0, %1;" : "=r"(hi) : "f"(a));
    float r = a - __uint_as_float(hi);
    asm("cvt.rna.tf32.f32 %0, %1;" : "=r"(lo) : "f"(r));
}
__device__ __forceinline__ void mma8(float* c, const u32* a, const u32* b) {
    asm("mma.sync.aligned.m16n8k8.row.col.f32.tf32.tf32.f32 "
        "{%0,%1,%2,%3}, {%4,%5,%6,%7}, {%8,%9}, {%0,%1,%2,%3};"
        : "+f"(c[0]), "+f"(c[1]), "+f"(c[2]), "+f"(c[3])
        : "r"(a[0]), "r"(a[1]), "r"(a[2]), "r"(a[3]), "r"(b[0]), "r"(b[1]));
}

__device__ float g_q[BATCH*NHEAD*SEQ*HDIM];
__device__ float g_k[BATCH*NHEAD*SEQ*HDIM];
__device__ float g_v[BATCH*NHEAD*SEQ*HDIM];
__device__ float g_h[MTOT*EMBED];

// ---------------------------------------------------------------------------
// 128x128 tf32-mma GEMM body. Smem = k-pair rows: A2*[pair][col] holds
// (k, k+4) as uint2, pair = (k div 8)*4 + (k mod 4). Staging ownership and
// global loads identical to R11 (row lr, k's lc8..lc8+7, two float4).
// 8 warps as 2(m) x 4(n); warp tile 64x32; 3 mma per tile per k8.
// ---------------------------------------------------------------------------
#define PROJ_MMA_BODY(APTR, WPTR)                                              \
    __shared__ uint2 A2h[8][PRW];                                              \
    __shared__ uint2 A2l[8][PRW];                                              \
    __shared__ uint2 B2h[8][PRW];                                              \
    __shared__ uint2 B2l[8][PRW];                                              \
    const int tid  = threadIdx.x;                                              \
    const int lane = tid & 31;                                                 \
    const int wid  = tid >> 5;                                                 \
    const int m0 = blockIdx.y * PBM;                                           \
    const int n0 = blockIdx.x * PBN;                                           \
    const int wm = (wid >> 2) << 6;                                            \
    const int wn = (wid & 3) << 5;                                             \
    const int g4 = lane >> 2;                                                  \
    const int t4 = lane & 3;                                                   \
    const int lr  = tid >> 1;                                                  \
    const int lc8 = (tid & 1) << 3;                                            \
    const int pbase = lc8 >> 1;              /* 0 or 4 */                      \
    const float* Ap = (APTR) + (size_t)(m0 + lr) * EMBED + lc8;                \
    const float* Wp = (WPTR) + (size_t)(n0 + lr) * EMBED + lc8;                \
    float c[4][4][4];                                                          \
    _Pragma("unroll")                                                          \
    for (int mi = 0; mi < 4; mi++)                                             \
        _Pragma("unroll")                                                      \
        for (int ni = 0; ni < 4; ni++)                                         \
            _Pragma("unroll")                                                  \
            for (int u = 0; u < 4; u++) c[mi][ni][u] = 0.f;                    \
    float4 a0 = *(const float4*)(Ap);                                          \
    float4 a1 = *(const float4*)(Ap + 4);                                      \
    float4 w0 = *(const float4*)(Wp);                                          \
    float4 w1 = *(const float4*)(Wp + 4);                                      \
    for (int kb = 0; kb < EMBED; kb += PBK) {                                  \
        __syncthreads();                                                       \
        {                                                                      \
            const float av0[4] = {a0.x, a0.y, a0.z, a0.w};                     \
            const float av1[4] = {a1.x, a1.y, a1.z, a1.w};                     \
            const float wv0[4] = {w0.x, w0.y, w0.z, w0.w};                     \
            const float wv1[4] = {w1.x, w1.y, w1.z, w1.w};                     \
            _Pragma("unroll")                                                  \
            for (int j = 0; j < 4; j++) {                                      \
                u32 h0, l0, h1, l1;                                            \
                split_tf32(av0[j], h0, l0);                                    \
                split_tf32(av1[j], h1, l1);                                    \
                A2h[pbase + j][lr] = make_uint2(h0, h1);                       \
                A2l[pbase + j][lr] = make_uint2(l0, l1);                       \
                split_tf32(wv0[j], h0, l0);                                    \
                split_tf32(wv1[j], h1, l1);                                    \
                B2h[pbase + j][lr] = make_uint2(h0, h1);                       \
                B2l[pbase + j][lr] = make_uint2(l0, l1);                       \
            }                                                                  \
        }                                                                      \
        __syncthreads();                                                       \
        if (kb + PBK < EMBED) {                                                \
            a0 = *(const float4*)(Ap + kb + PBK);                              \
            a1 = *(const float4*)(Ap + kb + PBK + 4);                          \
            w0 = *(const float4*)(Wp + kb + PBK);                              \
            w1 = *(const float4*)(Wp + kb + PBK + 4);                          \
        }                                                                      \
        _Pragma("unroll")                                                      \
        for (int k8 = 0; k8 < PBK; k8 += 8) {                                  \
            const int pr = (k8 >> 1) + t4;     /* 0..3 or 4..7 */              \
            u32 bhi[4][2], blo[4][2];                                          \
            _Pragma("unroll")                                                  \
            for (int ni = 0; ni < 4; ni++) {                                   \
                const int kc = wn + ni*8 + g4;                                 \
                uint2 ph = B2h[pr][kc];                                        \
                uint2 pl = B2l[pr][kc];                                        \
                bhi[ni][0] = ph.x; bhi[ni][1] = ph.y;                          \
                blo[ni][0] = pl.x; blo[ni][1] = pl.y;                          \
            }                                                                  \
            _Pragma("unroll")                                                  \
            for (int mi = 0; mi < 4; mi++) {                                   \
                const int r = wm + mi*16 + g4;                                 \
                uint2 hA = A2h[pr][r], hB = A2h[pr][r + 8];                    \
                uint2 lA = A2l[pr][r], lB = A2l[pr][r + 8];                    \
                u32 ahi[4] = {hA.x, hB.x, hA.y, hB.y};                         \
                u32 alo[4] = {lA.x, lB.x, lA.y, lB.y};                         \
                _Pragma("unroll")                                              \
                for (int ni = 0; ni < 4; ni++) {                               \
                    mma8(c[mi][ni], ahi, bhi[ni]);                             \
                    mma8(c[mi][ni], ahi, blo[ni]);                             \
                    mma8(c[mi][ni], alo, bhi[ni]);                             \
                }                                                              \
            }                                                                  \
        }                                                                      \
    }

// ---------------------------------------------------------------------------
__global__ __launch_bounds__(256, 2) void qkv_proj_kernel(
    const float* __restrict__ X,
    const float* __restrict__ Wq, const float* __restrict__ bq,
    const float* __restrict__ Wk, const float* __restrict__ bk,
    const float* __restrict__ Wv, const float* __restrict__ bv)
{
    const int z = blockIdx.z;
    const float *W, *bias; float* Out;
    if (z == 0)      { W = Wq; bias = bq; Out = g_q; }
    else if (z == 1) { W = Wk; bias = bk; Out = g_k; }
    else             { W = Wv; bias = bv; Out = g_v; }

    PROJ_MMA_BODY(X, W)

#pragma unroll
    for (int mi = 0; mi < 4; mi++) {
#pragma unroll
        for (int ni = 0; ni < 4; ni++) {
            const int col = n0 + wn + ni*8 + 2*t4;
            const int h   = col >> 6;
            const int d   = col & 63;
            float2 bb = *(const float2*)&bias[col];
#pragma unroll
            for (int half = 0; half < 2; half++) {
                int row = m0 + wm + mi*16 + g4 + half*8;
                int b   = row >> 11;
                int n   = row & (SEQ - 1);
                float2 o = make_float2(c[mi][ni][2*half+0] + bb.x,
                                       c[mi][ni][2*half+1] + bb.y);
                *(float2*)&Out[((size_t)(b*NHEAD + h)*SEQ + n)*HDIM + d] = o;
            }
        }
    }
}

// ---------------------------------------------------------------------------
__global__ __launch_bounds__(256, 2) void out_proj_kernel(
    const float* __restrict__ Wo, const float* __restrict__ bo,
    float* __restrict__ Outp)
{
    PROJ_MMA_BODY(g_h, Wo)

#pragma unroll
    for (int mi = 0; mi < 4; mi++) {
#pragma unroll
        for (int ni = 0; ni < 4; ni++) {
            const int col = n0 + wn + ni*8 + 2*t4;
            float2 bb = *(const float2*)&bo[col];
#pragma unroll
            for (int half = 0; half < 2; half++) {
                int row = m0 + wm + mi*16 + g4 + half*8;
                float2 o = make_float2(c[mi][ni][2*half+0] + bb.x,
                                       c[mi][ni][2*half+1] + bb.y);
                *(float2*)&Outp[(size_t)row * EMBED + col] = o;
            }
        }
    }
}

// ---------------------------------------------------------------------------
// Flash attention (R6 measured-best): f32x2 inner loops, shared K/V buffer.
// ---------------------------------------------------------------------------
__global__ __launch_bounds__(256, 2) void attn_kernel()
{
    extern __shared__ float sm[];
    float* Qs  = sm;
    float* KVs = sm + 64*PADP;
    float* Ps  = sm + 2*64*PADP;
    float* corr_s = sm + 3*64*PADP;
    float* l_s    = corr_s + 64;

    const int tid = threadIdx.x;
    const int bh  = blockIdx.y;
    const int q0  = blockIdx.x << 6;
    const float* Qg = g_q + (size_t)bh * SEQ * HDIM;
    const float* Kg = g_k + (size_t)bh * SEQ * HDIM;
    const float* Vg = g_v + (size_t)bh * SEQ * HDIM;

    const int lr = tid >> 2;
    const int ty = tid >> 4;
    const int tx = tid & 15;
    const int g   = tid >> 6;
    const int t64 = tid & 63;
    const int tr  = t64 >> 3;
    const int tc  = t64 & 7;

#pragma unroll
    for (int it = 0; it < 4; it++) {
        int d = it * 16 + ((tid & 3) << 2);
        float4 v = *(const float4*)&Qg[(size_t)(q0 + lr) * HDIM + d];
        Qs[(d+0)*PADP + lr] = v.x;  Qs[(d+1)*PADP + lr] = v.y;
        Qs[(d+2)*PADP + lr] = v.z;  Qs[(d+3)*PADP + lr] = v.w;
    }

    float m_run[4], l_run[4];
    u64 o2[8][4];
#pragma unroll
    for (int i = 0; i < 4; i++) { m_run[i] = -1e30f; l_run[i] = 0.f; }
#pragma unroll
    for (int i = 0; i < 8; i++)
#pragma unroll
        for (int j = 0; j < 4; j++) o2[i][j] = 0ull;

    for (int k0 = 0; k0 < SEQ; k0 += 64) {
        __syncthreads();
#pragma unroll
        for (int it = 0; it < 4; it++) {
            int d = it * 16 + ((tid & 3) << 2);
            float4 kv = *(const float4*)&Kg[(size_t)(k0 + lr) * HDIM + d];
            KVs[(d+0)*PADP + lr] = kv.x;  KVs[(d+1)*PADP + lr] = kv.y;
            KVs[(d+2)*PADP + lr] = kv.z;  KVs[(d+3)*PADP + lr] = kv.w;
        }
        __syncthreads();

        u64 s2[4][2] = {{0ull,0ull},{0ull,0ull},{0ull,0ull},{0ull,0ull}};
#pragma unroll 8
        for (int d = 0; d < 64; d++) {
            float4 av = *(const float4*)&Qs[d*PADP + (ty<<2)];
            const u64* bp = (const u64*)&KVs[d*PADP + (tx<<2)];
            u64 b0 = bp[0], b1 = bp[1];
            float ar[4] = {av.x, av.y, av.z, av.w};
#pragma unroll
            for (int i = 0; i < 4; i++) {
                u64 av2 = pk2(ar[i]);
                fma2(s2[i][0], av2, b0);
                fma2(s2[i][1], av2, b1);
            }
        }

#pragma unroll
        for (int i = 0; i < 4; i++) {
            float2 q0p = up2(s2[i][0]), q1p = up2(s2[i][1]);
            float s[4] = {q0p.x*8.0f, q0p.y*8.0f, q1p.x*8.0f, q1p.y*8.0f};
            float mx = fmaxf(fmaxf(s[0], s[1]), fmaxf(s[2], s[3]));
            mx = fmaxf(mx, __shfl_xor_sync(0xffffffffu, mx, 8, 16));
            mx = fmaxf(mx, __shfl_xor_sync(0xffffffffu, mx, 4, 16));
            mx = fmaxf(mx, __shfl_xor_sync(0xffffffffu, mx, 2, 16));
            mx = fmaxf(mx, __shfl_xor_sync(0xffffffffu, mx, 1, 16));
            float mnew = fmaxf(m_run[i], mx);
            float corr = __expf(m_run[i] - mnew);
            float rs = 0.f;
#pragma unroll
            for (int j = 0; j < 4; j++) {
                float p = __expf(s[j] - mnew);
                s[j] = p; rs += p;
            }
            rs += __shfl_xor_sync(0xffffffffu, rs, 8, 16);
            rs += __shfl_xor_sync(0xffffffffu, rs, 4, 16);
            rs += __shfl_xor_sync(0xffffffffu, rs, 2, 16);
            rs += __shfl_xor_sync(0xffffffffu, rs, 1, 16);
            l_run[i] = l_run[i] * corr + rs;
            m_run[i] = mnew;
            if (tx == 0) corr_s[(ty<<2)+i] = corr;
            *(float4*)&Ps[((ty<<2)+i)*PADP + (tx<<2)] =
                make_float4(s[0], s[1], s[2], s[3]);
        }
        __syncthreads();

#pragma unroll
        for (int it = 0; it < 4; it++) {
            int d = it * 16 + ((tid & 3) << 2);
            float4 vv = *(const float4*)&Vg[(size_t)(k0 + lr) * HDIM + d];
            *(float4*)&KVs[lr * PADP + d] = vv;
        }
        __syncthreads();

#pragma unroll
        for (int rr = 0; rr < 8; rr++) {
            u64 c2 = pk2(corr_s[tr*8 + rr]);
            mul2(o2[rr][0], c2); mul2(o2[rr][1], c2);
            mul2(o2[rr][2], c2); mul2(o2[rr][3], c2);
        }

        const int kbase = g << 4;
#pragma unroll
        for (int c4 = 0; c4 < 16; c4 += 4) {
            const int kk = kbase + c4;
            u64 v2[4][4];
#pragma unroll
            for (int u = 0; u < 4; u++) {
                const u64* vp0 = (const u64*)&KVs[(kk+u)*PADP + (tc<<2)];
                const u64* vp1 = (const u64*)&KVs[(kk+u)*PADP + 32 + (tc<<2)];
                v2[u][0] = vp0[0]; v2[u][1] = vp0[1];
                v2[u][2] = vp1[0]; v2[u][3] = vp1[1];
            }
#pragma unroll
            for (int rr = 0; rr < 8; rr++) {
                float4 p = *(const float4*)&Ps[(tr*8+rr)*PADP + kk];
                float pa[4] = {p.x, p.y, p.z, p.w};
#pragma unroll
                for (int u = 0; u < 4; u++) {
                    u64 p2 = pk2(pa[u]);
                    fma2(o2[rr][0], p2, v2[u][0]);
                    fma2(o2[rr][1], p2, v2[u][1]);
                    fma2(o2[rr][2], p2, v2[u][2]);
                    fma2(o2[rr][3], p2, v2[u][3]);
                }
            }
        }
    }

    float o[8][8];
#pragma unroll
    for (int rr = 0; rr < 8; rr++) {
        float2 p0 = up2(o2[rr][0]), p1 = up2(o2[rr][1]);
        float2 p2 = up2(o2[rr][2]), p3 = up2(o2[rr][3]);
        o[rr][0]=p0.x; o[rr][1]=p0.y; o[rr][2]=p1.x; o[rr][3]=p1.y;
        o[rr][4]=p2.x; o[rr][5]=p2.y; o[rr][6]=p3.x; o[rr][7]=p3.y;
    }

    if (tx == 0) {
#pragma unroll
        for (int i = 0; i < 4; i++) l_s[(ty<<2)+i] = l_run[i];
    }
    __syncthreads();

    if (g > 0) {
        float* mb = sm + (g-1)*(64*PADP) + t64*PADP;
#pragma unroll
        for (int rr = 0; rr < 8; rr++) {
            *(float4*)&mb[rr*8 + 0] = make_float4(o[rr][0], o[rr][1], o[rr][2], o[rr][3]);
            *(float4*)&mb[rr*8 + 4] = make_float4(o[rr][4], o[rr][5], o[rr][6], o[rr][7]);
        }
    }
    __syncthreads();

    if (g == 0) {
        const int b = bh >> 4;
        const int h = bh & 15;
#pragma unroll
        for (int gg = 0; gg < 3; gg++) {
            const float* mb = sm + gg*(64*PADP) + t64*PADP;
#pragma unroll
            for (int rr = 0; rr < 8; rr++) {
                float4 p0 = *(const float4*)&mb[rr*8 + 0];
                float4 p1 = *(const float4*)&mb[rr*8 + 4];
                o[rr][0] += p0.x; o[rr][1] += p0.y; o[rr][2] += p0.z; o[rr][3] += p0.w;
                o[rr][4] += p1.x; o[rr][5] += p1.y; o[rr][6] += p1.z; o[rr][7] += p1.w;
            }
        }
#pragma unroll
        for (int rr = 0; rr < 8; rr++) {
            int row = tr*8 + rr;
            float inv = 1.0f / l_s[row];
            int q = q0 + row;
            float* dst = &g_h[((size_t)(b*SEQ + q))*EMBED + h*HDIM];
            *(float4*)&dst[(tc<<2)] =
                make_float4(o[rr][0]*inv, o[rr][1]*inv, o[rr][2]*inv, o[rr][3]*inv);
            *(float4*)&dst[32 + (tc<<2)] =
                make_float4(o[rr][4]*inv, o[rr][5]*inv, o[rr][6]*inv, o[rr][7]*inv);
        }
    }
}

// ---------------------------------------------------------------------------
extern "C" void kernel_launch(void* const* d_in, const int* in_sizes, int n_in,
                              void* d_out, int out_size)
{
    const float* x  = (const float*)d_in[0];
    const float* Wq = (const float*)d_in[1];
    const float* bq = (const float*)d_in[2];
    const float* Wk = (const float*)d_in[3];
    const float* bk = (const float*)d_in[4];
    const float* Wv = (const float*)d_in[5];
    const float* bv = (const float*)d_in[6];
    const float* Wo = (const float*)d_in[7];
    const float* bo = (const float*)d_in[8];
    float* out = (float*)d_out;

    cudaFuncSetAttribute(attn_kernel,
                         cudaFuncAttributeMaxDynamicSharedMemorySize, ATTN_SMEM);

    dim3 gproj(EMBED / PBN, MTOT / PBM, 3);
    qkv_proj_kernel<<<gproj, 256>>>(x, Wq, bq, Wk, bk, Wv, bv);

    dim3 gattn(SEQ / 64, BATCH * NHEAD);
    attn_kernel<<<gattn, 256, ATTN_SMEM>>>();

    dim3 gout(EMBED / PBN, MTOT / PBM);
    out_proj_kernel<<<gout, 256>>>(Wo, bo, out);
}

// round 15
// speedup vs baseline: 1.0890x; 1.0551x over previous
#include <cuda_runtime.h>

// Round 15: projections = R11 exact (measured best, 524us qkv). Attention QK
// moved to tf32 mma with splits computed at SMEM STAGING time (global loads
// identical to R6; none of R9's 2x-traffic/extra-smem/epilogue costs).
// V overlays the Khi buffer after QK; 4 barriers/tile as R6. Softmax + f32x2
// PV unchanged (R9-proven index mapping).

#define EMBED 1024
#define NHEAD 16
#define HDIM  64
#define BATCH 2
#define SEQ   2048
#define MTOT  (BATCH*SEQ)

#define PBM 128
#define PBN 128
#define PBK 16
#define PADT 136

#define PADP 68
#define ATTN_FLOATS (5*64*PADP + 128)   // Qhi,Qlo,Khi(/V),Klo,Ps + corr/l
#define ATTN_SMEM   (ATTN_FLOATS*4)

typedef unsigned long long u64;
typedef unsigned int u32;

// ---- f32x2 helpers ----
__device__ __forceinline__ u64 pk2(float a) {
    u64 r; asm("mov.b64 %0, {%1, %1};" : "=l"(r) : "f"(a)); return r;
}
__device__ __forceinline__ void fma2(u64& d, u64 a, u64 b) {
    asm("fma.rn.f32x2 %0, %1, %2, %0;" : "+l"(d) : "l"(a), "l"(b));
}
__device__ __forceinline__ void mul2(u64& d, u64 a) {
    asm("mul.rn.f32x2 %0, %0, %1;" : "+l"(d) : "l"(a));
}
__device__ __forceinline__ float2 up2(u64 v) {
    float2 r; asm("mov.b64 {%0, %1}, %2;" : "=f"(r.x), "=f"(r.y) : "l"(v)); return r;
}

// ---- tf32 helpers ----
__device__ __forceinline__ void split_tf32(float a, u32& hi, u32& lo) {
    asm("cvt.rna.tf32.f32 %0, %1;" : "=r"(hi) : "f"(a));
    float r = a - __uint_as_float(hi);
    asm("cvt.rna.tf32.f32 %0, %1;" : "=r"(lo) : "f"(r));
}
__device__ __forceinline__ void mma8(float* c, const u32* a, const u32* b) {
    asm("mma.sync.aligned.m16n8k8.row.col.f32.tf32.tf32.f32 "
        "{%0,%1,%2,%3}, {%4,%5,%6,%7}, {%8,%9}, {%0,%1,%2,%3};"
        : "+f"(c[0]), "+f"(c[1]), "+f"(c[2]), "+f"(c[3])
        : "r"(a[0]), "r"(a[1]), "r"(a[2]), "r"(a[3]), "r"(b[0]), "r"(b[1]));
}

__device__ float g_q[BATCH*NHEAD*SEQ*HDIM];
__device__ float g_k[BATCH*NHEAD*SEQ*HDIM];
__device__ float g_v[BATCH*NHEAD*SEQ*HDIM];
__device__ float g_h[MTOT*EMBED];

// ---------------------------------------------------------------------------
// R11 projection GEMM body (measured best): split at STS time, scalar smem.
// ---------------------------------------------------------------------------
#define STS_SPLIT(DH, DL, J, V)                                                \
    { u32 _h, _l; split_tf32((V), _h, _l);                                     \
      DH[lc8+(J)][lr] = _h; DL[lc8+(J)][lr] = _l; }

#define PROJ_MMA_BODY(APTR, WPTR)                                              \
    __shared__ u32 Ash[PBK][PADT];                                             \
    __shared__ u32 Asl[PBK][PADT];                                             \
    __shared__ u32 Bsh[PBK][PADT];                                             \
    __shared__ u32 Bsl[PBK][PADT];                                             \
    const int tid  = threadIdx.x;                                              \
    const int lane = tid & 31;                                                 \
    const int wid  = tid >> 5;                                                 \
    const int m0 = blockIdx.y * PBM;                                           \
    const int n0 = blockIdx.x * PBN;                                           \
    const int wm = (wid >> 2) << 6;                                            \
    const int wn = (wid & 3) << 5;                                             \
    const int g4 = lane >> 2;                                                  \
    const int t4 = lane & 3;                                                   \
    const int lr  = tid >> 1;                                                  \
    const int lc8 = (tid & 1) << 3;                                            \
    const float* Ap = (APTR) + (size_t)(m0 + lr) * EMBED + lc8;                \
    const float* Wp = (WPTR) + (size_t)(n0 + lr) * EMBED + lc8;                \
    float c[4][4][4];                                                          \
    _Pragma("unroll")                                                          \
    for (int mi = 0; mi < 4; mi++)                                             \
        _Pragma("unroll")                                                      \
        for (int ni = 0; ni < 4; ni++)                                         \
            _Pragma("unroll")                                                  \
            for (int u = 0; u < 4; u++) c[mi][ni][u] = 0.f;                    \
    float4 a0 = *(const float4*)(Ap);                                          \
    float4 a1 = *(const float4*)(Ap + 4);                                      \
    float4 w0 = *(const float4*)(Wp);                                          \
    float4 w1 = *(const float4*)(Wp + 4);                                      \
    for (int kb = 0; kb < EMBED; kb += PBK) {                                  \
        __syncthreads();                                                       \
        STS_SPLIT(Ash, Asl, 0, a0.x)  STS_SPLIT(Ash, Asl, 1, a0.y)             \
        STS_SPLIT(Ash, Asl, 2, a0.z)  STS_SPLIT(Ash, Asl, 3, a0.w)             \
        STS_SPLIT(Ash, Asl, 4, a1.x)  STS_SPLIT(Ash, Asl, 5, a1.y)             \
        STS_SPLIT(Ash, Asl, 6, a1.z)  STS_SPLIT(Ash, Asl, 7, a1.w)             \
        STS_SPLIT(Bsh, Bsl, 0, w0.x)  STS_SPLIT(Bsh, Bsl, 1, w0.y)             \
        STS_SPLIT(Bsh, Bsl, 2, w0.z)  STS_SPLIT(Bsh, Bsl, 3, w0.w)             \
        STS_SPLIT(Bsh, Bsl, 4, w1.x)  STS_SPLIT(Bsh, Bsl, 5, w1.y)             \
        STS_SPLIT(Bsh, Bsl, 6, w1.z)  STS_SPLIT(Bsh, Bsl, 7, w1.w)             \
        __syncthreads();                                                       \
        if (kb + PBK < EMBED) {                                                \
            a0 = *(const float4*)(Ap + kb + PBK);                              \
            a1 = *(const float4*)(Ap + kb + PBK + 4);                          \
            w0 = *(const float4*)(Wp + kb + PBK);                              \
            w1 = *(const float4*)(Wp + kb + PBK + 4);                          \
        }                                                                      \
        _Pragma("unroll")                                                      \
        for (int k8 = 0; k8 < PBK; k8 += 8) {                                  \
            u32 bhi[4][2], blo[4][2];                                          \
            _Pragma("unroll")                                                  \
            for (int ni = 0; ni < 4; ni++) {                                   \
                const int kc = wn + ni*8 + g4;                                 \
                bhi[ni][0] = Bsh[k8 + t4    ][kc];                             \
                bhi[ni][1] = Bsh[k8 + t4 + 4][kc];                             \
                blo[ni][0] = Bsl[k8 + t4    ][kc];                             \
                blo[ni][1] = Bsl[k8 + t4 + 4][kc];                             \
            }                                                                  \
            _Pragma("unroll")                                                  \
            for (int mi = 0; mi < 4; mi++) {                                   \
                const int r = wm + mi*16 + g4;                                 \
                u32 ahi[4], alo[4];                                            \
                ahi[0] = Ash[k8 + t4    ][r];                                  \
                ahi[1] = Ash[k8 + t4    ][r + 8];                              \
                ahi[2] = Ash[k8 + t4 + 4][r];                                  \
                ahi[3] = Ash[k8 + t4 + 4][r + 8];                              \
                alo[0] = Asl[k8 + t4    ][r];                                  \
                alo[1] = Asl[k8 + t4    ][r + 8];                              \
                alo[2] = Asl[k8 + t4 + 4][r];                                  \
                alo[3] = Asl[k8 + t4 + 4][r + 8];                              \
                _Pragma("unroll")                                              \
                for (int ni = 0; ni < 4; ni++) {                               \
                    mma8(c[mi][ni], ahi, bhi[ni]);                             \
                    mma8(c[mi][ni], ahi, blo[ni]);                             \
                    mma8(c[mi][ni], alo, bhi[ni]);                             \
                }                                                              \
            }                                                                  \
        }                                                                      \
    }

// ---------------------------------------------------------------------------
__global__ __launch_bounds__(256, 2) void qkv_proj_kernel(
    const float* __restrict__ X,
    const float* __restrict__ Wq, const float* __restrict__ bq,
    const float* __restrict__ Wk, const float* __restrict__ bk,
    const float* __restrict__ Wv, const float* __restrict__ bv)
{
    const int z = blockIdx.z;
    const float *W, *bias; float* Out;
    if (z == 0)      { W = Wq; bias = bq; Out = g_q; }
    else if (z == 1) { W = Wk; bias = bk; Out = g_k; }
    else             { W = Wv; bias = bv; Out = g_v; }

    PROJ_MMA_BODY(X, W)

#pragma unroll
    for (int mi = 0; mi < 4; mi++) {
#pragma unroll
        for (int ni = 0; ni < 4; ni++) {
            const int col = n0 + wn + ni*8 + 2*t4;
            const int h   = col >> 6;
            const int d   = col & 63;
            float2 bb = *(const float2*)&bias[col];
#pragma unroll
            for (int half = 0; half < 2; half++) {
                int row = m0 + wm + mi*16 + g4 + half*8;
                int b   = row >> 11;
                int n   = row & (SEQ - 1);
                float2 o = make_float2(c[mi][ni][2*half+0] + bb.x,
                                       c[mi][ni][2*half+1] + bb.y);
                *(float2*)&Out[((size_t)(b*NHEAD + h)*SEQ + n)*HDIM + d] = o;
            }
        }
    }
}

// ---------------------------------------------------------------------------
__global__ __launch_bounds__(256, 2) void out_proj_kernel(
    const float* __restrict__ Wo, const float* __restrict__ bo,
    float* __restrict__ Outp)
{
    PROJ_MMA_BODY(g_h, Wo)

#pragma unroll
    for (int mi = 0; mi < 4; mi++) {
#pragma unroll
        for (int ni = 0; ni < 4; ni++) {
            const int col = n0 + wn + ni*8 + 2*t4;
            float2 bb = *(const float2*)&bo[col];
#pragma unroll
            for (int half = 0; half < 2; half++) {
                int row = m0 + wm + mi*16 + g4 + half*8;
                float2 o = make_float2(c[mi][ni][2*half+0] + bb.x,
                                       c[mi][ni][2*half+1] + bb.y);
                *(float2*)&Outp[(size_t)row * EMBED + col] = o;
            }
        }
    }
}

// ---------------------------------------------------------------------------
// Flash attention: QK via tf32 mma (split at staging), SIMT softmax, f32x2 PV.
// Smem: Qhi, Qlo, Khi(->V after QK), Klo, Ps. 4 barriers/tile.
// ---------------------------------------------------------------------------
__global__ __launch_bounds__(256, 2) void attn_kernel()
{
    extern __shared__ float sm[];
    u32*   Qhi = (u32*)sm;
    u32*   Qlo = (u32*)(sm + 64*PADP);
    u32*   Khi = (u32*)(sm + 2*64*PADP);
    u32*   Klo = (u32*)(sm + 3*64*PADP);
    float* Vs  = sm + 2*64*PADP;          // overlays Khi after QK
    float* Ps  = sm + 4*64*PADP;
    float* corr_s = sm + 5*64*PADP;
    float* l_s    = corr_s + 64;

    const int tid  = threadIdx.x;
    const int lane = tid & 31;
    const int wid  = tid >> 5;
    const int bh  = blockIdx.y;
    const int q0  = blockIdx.x << 6;
    const size_t base = (size_t)bh * SEQ * HDIM;
    const float* Qg = g_q + base;
    const float* Kg = g_k + base;
    const float* Vg = g_v + base;

    const int lr = tid >> 2;           // staging row 0..63
    const int dq = (tid & 3) << 4;     // staging d-offset (16 elems)
    const int ty = tid >> 4;           // softmax mapping
    const int tx = tid & 15;
    const int g   = tid >> 6;          // PV key-split group
    const int t64 = tid & 63;
    const int tr  = t64 >> 3;
    const int tc  = t64 & 7;
    // QK mma mapping: 8 warps = 4(m) x 2(n)
    const int qm0 = (wid >> 1) << 4;
    const int wn  = (wid & 1) << 5;
    const int g4  = lane >> 2;
    const int t4  = lane & 3;

    // Stage Q once: fp32 load (R6 pattern), split -> Qhi/Qlo [q][d]
#pragma unroll
    for (int it = 0; it < 4; it++) {
        float4 v = *(const float4*)&Qg[(size_t)(q0 + lr)*HDIM + dq + it*4];
        uint4 h, l;
        split_tf32(v.x, h.x, l.x); split_tf32(v.y, h.y, l.y);
        split_tf32(v.z, h.z, l.z); split_tf32(v.w, h.w, l.w);
        *(uint4*)&Qhi[lr*PADP + dq + it*4] = h;
        *(uint4*)&Qlo[lr*PADP + dq + it*4] = l;
    }

    float m_run[4], l_run[4];
    u64 o2[8][4];
#pragma unroll
    for (int i = 0; i < 4; i++) { m_run[i] = -1e30f; l_run[i] = 0.f; }
#pragma unroll
    for (int i = 0; i < 8; i++)
#pragma unroll
        for (int j = 0; j < 4; j++) o2[i][j] = 0ull;

    for (int k0 = 0; k0 < SEQ; k0 += 64) {
        __syncthreads();   // (1) prev PV done; Q staged (iter 0)
        // Stage K: fp32 load (R6 pattern), split -> Khi/Klo [k][d]
#pragma unroll
        for (int it = 0; it < 4; it++) {
            float4 v = *(const float4*)&Kg[(size_t)(k0 + lr)*HDIM + dq + it*4];
            uint4 h, l;
            split_tf32(v.x, h.x, l.x); split_tf32(v.y, h.y, l.y);
            split_tf32(v.z, h.z, l.z); split_tf32(v.w, h.w, l.w);
            *(uint4*)&Khi[lr*PADP + dq + it*4] = h;
            *(uint4*)&Klo[lr*PADP + dq + it*4] = l;
        }
        __syncthreads();   // (2) K ready

        // ---- S = Q K^T via 3xTF32 mma (R9-proven mapping) ----
        float c[4][4];
#pragma unroll
        for (int ni = 0; ni < 4; ni++)
#pragma unroll
            for (int u = 0; u < 4; u++) c[ni][u] = 0.f;

#pragma unroll
        for (int k8 = 0; k8 < 64; k8 += 8) {
            u32 ahi[4], alo[4];
            ahi[0] = Qhi[(qm0+g4  )*PADP + k8 + t4    ];
            ahi[1] = Qhi[(qm0+g4+8)*PADP + k8 + t4    ];
            ahi[2] = Qhi[(qm0+g4  )*PADP + k8 + t4 + 4];
            ahi[3] = Qhi[(qm0+g4+8)*PADP + k8 + t4 + 4];
            alo[0] = Qlo[(qm0+g4  )*PADP + k8 + t4    ];
            alo[1] = Qlo[(qm0+g4+8)*PADP + k8 + t4    ];
            alo[2] = Qlo[(qm0+g4  )*PADP + k8 + t4 + 4];
            alo[3] = Qlo[(qm0+g4+8)*PADP + k8 + t4 + 4];
#pragma unroll
            for (int ni = 0; ni < 4; ni++) {
                const int kr = wn + ni*8 + g4;
                u32 bhi[2], blo[2];
                bhi[0] = Khi[kr*PADP + k8 + t4];
                bhi[1] = Khi[kr*PADP + k8 + t4 + 4];
                blo[0] = Klo[kr*PADP + k8 + t4];
                blo[1] = Klo[kr*PADP + k8 + t4 + 4];
                mma8(c[ni], ahi, bhi);
                mma8(c[ni], ahi, blo);
                mma8(c[ni], alo, bhi);
            }
        }

        // write raw S fragments to Ps
#pragma unroll
        for (int ni = 0; ni < 4; ni++) {
            const int col = wn + ni*8 + 2*t4;
            *(float2*)&Ps[(qm0+g4  )*PADP + col] = make_float2(c[ni][0], c[ni][1]);
            *(float2*)&Ps[(qm0+g4+8)*PADP + col] = make_float2(c[ni][2], c[ni][3]);
        }
        __syncthreads();   // (3) S complete; K buffers free

        // ---- online softmax (R6/R9 SIMT) + stage V into Khi region ----
#pragma unroll
        for (int i = 0; i < 4; i++) {
            float4 sv = *(const float4*)&Ps[((ty<<2)+i)*PADP + (tx<<2)];
            float s[4] = {sv.x*8.0f, sv.y*8.0f, sv.z*8.0f, sv.w*8.0f};
            float mx = fmaxf(fmaxf(s[0], s[1]), fmaxf(s[2], s[3]));
            mx = fmaxf(mx, __shfl_xor_sync(0xffffffffu, mx, 8, 16));
            mx = fmaxf(mx, __shfl_xor_sync(0xffffffffu, mx, 4, 16));
            mx = fmaxf(mx, __shfl_xor_sync(0xffffffffu, mx, 2, 16));
            mx = fmaxf(mx, __shfl_xor_sync(0xffffffffu, mx, 1, 16));
            float mnew = fmaxf(m_run[i], mx);
            float corr = __expf(m_run[i] - mnew);
            float rs = 0.f;
#pragma unroll
            for (int j = 0; j < 4; j++) {
                float p = __expf(s[j] - mnew);
                s[j] = p; rs += p;
            }
            rs += __shfl_xor_sync(0xffffffffu, rs, 8, 16);
            rs += __shfl_xor_sync(0xffffffffu, rs, 4, 16);
            rs += __shfl_xor_sync(0xffffffffu, rs, 2, 16);
            rs += __shfl_xor_sync(0xffffffffu, rs, 1, 16);
            l_run[i] = l_run[i] * corr + rs;
            m_run[i] = mnew;
            if (tx == 0) corr_s[(ty<<2)+i] = corr;
            *(float4*)&Ps[((ty<<2)+i)*PADP + (tx<<2)] =
                make_float4(s[0], s[1], s[2], s[3]);
        }
        // V stage (fp32, [k][d]) into Khi region
#pragma unroll
        for (int it = 0; it < 4; it++) {
            float4 vv = *(const float4*)&Vg[(size_t)(k0 + lr)*HDIM + dq + it*4];
            *(float4*)&Vs[lr*PADP + dq + it*4] = vv;
        }
        __syncthreads();   // (4) P, corr, V ready

        // ---- PV (f32x2 SIMT, 4-way key split) ----
#pragma unroll
        for (int rr = 0; rr < 8; rr++) {
            u64 c2 = pk2(corr_s[tr*8 + rr]);
            mul2(o2[rr][0], c2); mul2(o2[rr][1], c2);
            mul2(o2[rr][2], c2); mul2(o2[rr][3], c2);
        }

        const int kbase = g << 4;
#pragma unroll
        for (int c4 = 0; c4 < 16; c4 += 4) {
            const int kk = kbase + c4;
            u64 v2[4][4];
#pragma unroll
            for (int u = 0; u < 4; u++) {
                const u64* vp0 = (const u64*)&Vs[(kk+u)*PADP + (tc<<2)];
                const u64* vp1 = (const u64*)&Vs[(kk+u)*PADP + 32 + (tc<<2)];
                v2[u][0] = vp0[0]; v2[u][1] = vp0[1];
                v2[u][2] = vp1[0]; v2[u][3] = vp1[1];
            }
#pragma unroll
            for (int rr = 0; rr < 8; rr++) {
                float4 p = *(const float4*)&Ps[(tr*8+rr)*PADP + kk];
                float pa[4] = {p.x, p.y, p.z, p.w};
#pragma unroll
                for (int u = 0; u < 4; u++) {
                    u64 p2 = pk2(pa[u]);
                    fma2(o2[rr][0], p2, v2[u][0]);
                    fma2(o2[rr][1], p2, v2[u][1]);
                    fma2(o2[rr][2], p2, v2[u][2]);
                    fma2(o2[rr][3], p2, v2[u][3]);
                }
            }
        }
    }

    // unpack accumulators
    float o[8][8];
#pragma unroll
    for (int rr = 0; rr < 8; rr++) {
        float2 p0 = up2(o2[rr][0]), p1 = up2(o2[rr][1]);
        float2 p2 = up2(o2[rr][2]), p3 = up2(o2[rr][3]);
        o[rr][0]=p0.x; o[rr][1]=p0.y; o[rr][2]=p1.x; o[rr][3]=p1.y;
        o[rr][4]=p2.x; o[rr][5]=p2.y; o[rr][6]=p3.x; o[rr][7]=p3.y;
    }

    if (tx == 0) {
#pragma unroll
        for (int i = 0; i < 4; i++) l_s[(ty<<2)+i] = l_run[i];
    }
    __syncthreads();   // PV done; Qhi/Qlo/Khi regions reusable as merge bufs

    if (g > 0) {
        float* mb = sm + (g-1)*(64*PADP) + t64*PADP;
#pragma unroll
        for (int rr = 0; rr < 8; rr++) {
            *(float4*)&mb[rr*8 + 0] = make_float4(o[rr][0], o[rr][1], o[rr][2], o[rr][3]);
            *(float4*)&mb[rr*8 + 4] = make_float4(o[rr][4], o[rr][5], o[rr][6], o[rr][7]);
        }
    }
    __syncthreads();

    if (g == 0) {
        const int b = bh >> 4;
        const int h = bh & 15;
#pragma unroll
        for (int gg = 0; gg < 3; gg++) {
            const float* mb = sm + gg*(64*PADP) + t64*PADP;
#pragma unroll
            for (int rr = 0; rr < 8; rr++) {
                float4 p0 = *(const float4*)&mb[rr*8 + 0];
                float4 p1 = *(const float4*)&mb[rr*8 + 4];
                o[rr][0] += p0.x; o[rr][1] += p0.y; o[rr][2] += p0.z; o[rr][3] += p0.w;
                o[rr][4] += p1.x; o[rr][5] += p1.y; o[rr][6] += p1.z; o[rr][7] += p1.w;
            }
        }
#pragma unroll
        for (int rr = 0; rr < 8; rr++) {
            int row = tr*8 + rr;
            float inv = 1.0f / l_s[row];
            int q = q0 + row;
            float* dst = &g_h[((size_t)(b*SEQ + q))*EMBED + h*HDIM];
            *(float4*)&dst[(tc<<2)] =
                make_float4(o[rr][0]*inv, o[rr][1]*inv, o[rr][2]*inv, o[rr][3]*inv);
            *(float4*)&dst[32 + (tc<<2)] =
                make_float4(o[rr][4]*inv, o[rr][5]*inv, o[rr][6]*inv, o[rr][7]*inv);
        }
    }
}

// ---------------------------------------------------------------------------
extern "C" void kernel_launch(void* const* d_in, const int* in_sizes, int n_in,
                              void* d_out, int out_size)
{
    const float* x  = (const float*)d_in[0];
    const float* Wq = (const float*)d_in[1];
    const float* bq = (const float*)d_in[2];
    const float* Wk = (const float*)d_in[3];
    const float* bk = (const float*)d_in[4];
    const float* Wv = (const float*)d_in[5];
    const float* bv = (const float*)d_in[6];
    const float* Wo = (const float*)d_in[7];
    const float* bo = (const float*)d_in[8];
    float* out = (float*)d_out;

    cudaFuncSetAttribute(attn_kernel,
                         cudaFuncAttributeMaxDynamicSharedMemorySize, ATTN_SMEM);

    dim3 gproj(EMBED / PBN, MTOT / PBM, 3);
    qkv_proj_kernel<<<gproj, 256>>>(x, Wq, bq, Wk, bk, Wv, bv);

    dim3 gattn(SEQ / 64, BATCH * NHEAD);
    attn_kernel<<<gattn, 256, ATTN_SMEM>>>();

    dim3 gout(EMBED / PBN, MTOT / PBM);
    out_proj_kernel<<<gout, 256>>>(Wo, bo, out);
}